// round 15
// baseline (speedup 1.0000x reference)
#include <cuda_runtime.h>
#include <cuda_fp16.h>
#include <cstdint>
#include <cstddef>

// ----- problem constants -----
#define LSITES  784
#define CHI     128
#define BATCH   1024
#define NCLS    10
#define WROW    264               // padded k-stride of transposed W (halves)
#define SITE_HALVES (CHI * WROW)  // 33792 halves per site
#define SITE_BYTES  (SITE_HALVES * 2)  // 67584 B per site
#define BC      32                // samples per CTA (2 slabs of 16)
#define SLAB    16
#define NCTA    (BATCH / BC)      // 32
#define THREADS 512
#define HROW    132               // classifier h row stride (floats)
#define AROW    136               // padded A row stride (halves), K=128
#define ABUF_HALVES (SLAB * AROW) // 2176 halves per slab buffer
#define ABUF_BYTES  (ABUF_HALVES * 2)   // 4352
#define SMEM_A_OFF   (2 * SITE_BYTES)               // 135168
#define SMEM_MB_OFF  (SMEM_A_OFF + 4 * ABUF_BYTES)  // 152576
#define SMEM_TOTAL   (SMEM_MB_OFF + 32)             // 152608
// mbar layout: +0 full0, +8 full1 (count 1, tx); +16 empty0, +24 empty1 (count 2)

// fp16 transposed weights: Wt[site][b][k], k = s*128 + a, row stride WROW
__device__ __half g_Wt[(size_t)LSITES * SITE_HALVES];   // ~50.5 MB static scratch

// ---------------------------------------------------------------------------
// Prepass: W fp32 [n][s][a][b]  ->  fp16 Wt [n][b][k=s*128+a], padded rows
// ---------------------------------------------------------------------------
__global__ void __launch_bounds__(256) prep_kernel(const float* __restrict__ W) {
    extern __shared__ __half sw[];   // [256][132] halves
    const int n   = blockIdx.x;
    const int tid = threadIdx.x;
    const float* Wg = W + (size_t)n * (2 * CHI * CHI);

    for (int i = 0; i < 128; ++i) {
        int e = i * 256 + tid;
        int k = e >> 7;
        int b = e & 127;
        sw[k * 132 + b] = __float2half_rn(Wg[e]);
    }
    __syncthreads();

    const int w    = tid >> 5;
    const int lane = tid & 31;
    for (int r = 0; r < 16; ++r) {
        int b  = w * 16 + r;
        int k0 = lane * 8;
        __align__(16) __half tmp[8];
#pragma unroll
        for (int j = 0; j < 8; ++j) tmp[j] = sw[(k0 + j) * 132 + b];
        *(uint4*)(&g_Wt[((size_t)n * CHI + b) * WROW + k0]) = *(uint4*)tmp;
    }
}

// ---------------------------------------------------------------------------
__device__ __forceinline__ void mbar_wait(uint32_t mbar, uint32_t parity) {
    asm volatile(
        "{\n\t.reg .pred P;\n"
        "W%=:\n\t"
        "mbarrier.try_wait.parity.acquire.cta.shared::cta.b64 P, [%0], %1, 0x989680;\n\t"
        "@!P bra W%=;\n\t}"
        :: "r"(mbar), "r"(parity) : "memory");
}

// ---------------------------------------------------------------------------
// Main kernel: two independent 16-sample slab pipelines (warps 0-7 / 8-15),
// each byte-identical to the R4 consumer. Slabs are clock-DECOUPLED: no
// full-CTA barrier in the loop; per-slab named barriers handle the A-buffer
// WAR; the shared W double buffer is coordinated by full(tx)/empty mbarriers
// with producer-side-only backpressure.
// ---------------------------------------------------------------------------
__global__ void __launch_bounds__(THREADS, 1) mps_kernel(const float* __restrict__ x,
                                                         const float* __restrict__ V,
                                                         float* __restrict__ out) {
    extern __shared__ char smem[];
    __half* Wbuf = (__half*)smem;                       // [2][SITE_HALVES]
    __half* Abuf = (__half*)(smem + SMEM_A_OFF);        // [2 slab][2 buf][ABUF_HALVES]
    const uint32_t mb = (uint32_t)__cvta_generic_to_shared(smem + SMEM_MB_OFF);

    const int tid  = threadIdx.x;
    const int cta  = blockIdx.x;
    const int kg   = tid >> 8;               // slab 0/1 (warps 0-7 / 8-15)
    const int wt   = tid & 255;
    const int w    = wt >> 5;                // warp 0..7 within slab
    const int lane = tid & 31;
    const int g    = lane >> 2;              // 0..7
    const int tg   = lane & 3;               // 0..3
    const int c0   = w * 16 + 2 * tg;        // owned h/delta column base
    const int barid = 4 + kg;                // per-slab named barrier

    // h register layout (matches acc fragments)
    float h[8];
#pragma unroll
    for (int i = 0; i < 8; ++i) h[i] = 1.0f;

    if (tid == 0) {
        asm volatile("mbarrier.init.shared.b64 [%0], 1;" :: "r"(mb)      : "memory");
        asm volatile("mbarrier.init.shared.b64 [%0], 1;" :: "r"(mb + 8)  : "memory");
        asm volatile("mbarrier.init.shared.b64 [%0], 2;" :: "r"(mb + 16) : "memory");
        asm volatile("mbarrier.init.shared.b64 [%0], 2;" :: "r"(mb + 24) : "memory");
    }

    // init this slab's Abuf[buf 0] = fp16(1)
    {
        const __half one = __float2half_rn(1.f);
        __half* a0 = Abuf + kg * 2 * ABUF_HALVES;
        for (int i = wt; i < ABUF_HALVES; i += 256) a0[i] = one;
    }
    __syncthreads();   // barriers + A init visible to all (outside the loop)

    const uint32_t wbuf_s = (uint32_t)__cvta_generic_to_shared(Wbuf);
    const uint32_t abuf_s = (uint32_t)__cvta_generic_to_shared(Abuf);

    // prologue: stage site 0 into W buffer 0 (tid 0)
    if (tid == 0) {
        asm volatile("mbarrier.arrive.expect_tx.shared.b64 _, [%0], %1;"
                     :: "r"(mb), "r"((uint32_t)SITE_BYTES) : "memory");
        asm volatile(
            "cp.async.bulk.shared::cluster.global.mbarrier::complete_tx::bytes [%0], [%1], %2, [%3];"
            :: "r"(wbuf_s), "l"((const void*)g_Wt), "r"((uint32_t)SITE_BYTES), "r"(mb)
            : "memory");
    }

    // per-thread x streams
    const int sg0 = cta * BC + kg * SLAB + g;
    const int sg1 = sg0 + 8;
    const float* px00 = x + ((size_t)sg0 * 2 + 0) * LSITES;
    const float* px01 = x + ((size_t)sg0 * 2 + 1) * LSITES;
    const float* px10 = x + ((size_t)sg1 * 2 + 0) * LSITES;
    const float* px11 = x + ((size_t)sg1 * 2 + 1) * LSITES;
    float cx00 = __ldg(px00), cx01 = __ldg(px01);
    float cx10 = __ldg(px10), cx11 = __ldg(px11);

    // ldmatrix lane addresses
    const uint32_t a_base = abuf_s + (uint32_t)(kg * 2 * ABUF_BYTES) +
        (uint32_t)((((lane & 15) * AROW) + ((lane >> 4) * 8)) * 2);
    const int grp = lane >> 3;
    const int r8  = lane & 7;
    const int bn  = w * 16 + ((grp & 2) ? 8 : 0) + r8;
    const int bk  = (grp & 1) ? 8 : 0;
    const uint32_t b_base = wbuf_s + (uint32_t)((bn * WROW + bk) * 2);

    uint32_t phF0 = 0, phF1 = 0;   // per-slab full parities
    uint32_t phE0 = 0, phE1 = 0;   // tid0 empty parities

    for (int n = 0; n < LSITES; ++n) {
        const int p = n & 1;

        // tid 0: stage site n+1 into buffer 1-p (producer-side backpressure)
        if (tid == 0 && n + 1 < LSITES) {
            const uint32_t q = 1 - p;
            if (n >= 1) {   // WAR vs both slabs' reads of buffer 1-p at site n-1
                const uint32_t eb = mb + 16 + q * 8;
                if (q) { mbar_wait(eb, phE1); phE1 ^= 1; }
                else   { mbar_wait(eb, phE0); phE0 ^= 1; }
            }
            const uint32_t mnext = mb + q * 8;
            asm volatile("mbarrier.arrive.expect_tx.shared.b64 _, [%0], %1;"
                         :: "r"(mnext), "r"((uint32_t)SITE_BYTES) : "memory");
            asm volatile(
                "cp.async.bulk.shared::cluster.global.mbarrier::complete_tx::bytes [%0], [%1], %2, [%3];"
                :: "r"(wbuf_s + (uint32_t)(q * SITE_BYTES)),
                   "l"((const void*)(g_Wt + (size_t)(n + 1) * SITE_HALVES)),
                   "r"((uint32_t)SITE_BYTES), "r"(mnext)
                : "memory");
        }

        // prefetch x for next site
        float nx00 = 0.f, nx01 = 0.f, nx10 = 0.f, nx11 = 0.f;
        if (n + 1 < LSITES) {
            nx00 = __ldg(px00 + n + 1); nx01 = __ldg(px01 + n + 1);
            nx10 = __ldg(px10 + n + 1); nx11 = __ldg(px11 + n + 1);
        }

        // A fragments: this slab's 8 k-chunks of fp16(h)
        uint32_t a[8][4];
        {
            const uint32_t ab = a_base + (uint32_t)(p * ABUF_BYTES);
#pragma unroll
            for (int ca = 0; ca < 8; ++ca) {
                asm volatile(
                    "ldmatrix.sync.aligned.m8n8.x4.shared.b16 {%0,%1,%2,%3}, [%4];\n"
                    : "=r"(a[ca][0]), "=r"(a[ca][1]), "=r"(a[ca][2]), "=r"(a[ca][3])
                    : "r"(ab + (uint32_t)(ca * 32)));
            }
        }

        // wait for this site's W buffer (per-slab parity; no cross-slab align)
        if (p) { mbar_wait(mb + 8, phF1); phF1 ^= 1; }
        else   { mbar_wait(mb,     phF0); phF0 ^= 1; }

        // two GEMMs (s = k-half), 4 independent acc chains of depth 8
        float acc0[8], acc1[8];
#pragma unroll
        for (int i = 0; i < 8; ++i) { acc0[i] = 0.f; acc1[i] = 0.f; }
        {
            const uint32_t bl = b_base + (uint32_t)(p * SITE_BYTES);
#pragma unroll
            for (int c = 0; c < 16; ++c) {
                const int ca = c & 7;
                float* acc = (c & 8) ? acc1 : acc0;
                uint32_t b0, b1, b2, b3;
                asm volatile(
                    "ldmatrix.sync.aligned.m8n8.x4.shared.b16 {%0,%1,%2,%3}, [%4];\n"
                    : "=r"(b0), "=r"(b1), "=r"(b2), "=r"(b3)
                    : "r"(bl + (uint32_t)(c * 32)));
                asm volatile(
                    "mma.sync.aligned.m16n8k16.row.col.f32.f16.f16.f32 "
                    "{%0,%1,%2,%3}, {%4,%5,%6,%7}, {%8,%9}, {%0,%1,%2,%3};\n"
                    : "+f"(acc[0]), "+f"(acc[1]), "+f"(acc[2]), "+f"(acc[3])
                    : "r"(a[ca][0]), "r"(a[ca][1]), "r"(a[ca][2]), "r"(a[ca][3]),
                      "r"(b0), "r"(b1));
                asm volatile(
                    "mma.sync.aligned.m16n8k16.row.col.f32.f16.f16.f32 "
                    "{%0,%1,%2,%3}, {%4,%5,%6,%7}, {%8,%9}, {%0,%1,%2,%3};\n"
                    : "+f"(acc[4]), "+f"(acc[5]), "+f"(acc[6]), "+f"(acc[7])
                    : "r"(a[ca][0]), "r"(a[ca][1]), "r"(a[ca][2]), "r"(a[ca][3]),
                      "r"(b2), "r"(b3));
            }
        }

        // fold: h += x0[row]*delta0 + x1[row]*delta1   (f32, register-only)
        h[0] += cx00 * acc0[0] + cx01 * acc1[0];
        h[1] += cx00 * acc0[1] + cx01 * acc1[1];
        h[2] += cx10 * acc0[2] + cx11 * acc1[2];
        h[3] += cx10 * acc0[3] + cx11 * acc1[3];
        h[4] += cx00 * acc0[4] + cx01 * acc1[4];
        h[5] += cx00 * acc0[5] + cx01 * acc1[5];
        h[6] += cx10 * acc0[6] + cx11 * acc1[6];
        h[7] += cx10 * acc0[7] + cx11 * acc1[7];

        // publish fp16(h) into this slab's next A buffer
        {
            __half* ad = Abuf + kg * 2 * ABUF_HALVES + (1 - p) * ABUF_HALVES;
            *(__half2*)(ad + g * AROW + c0)           = __floats2half2_rn(h[0], h[1]);
            *(__half2*)(ad + g * AROW + c0 + 8)       = __floats2half2_rn(h[4], h[5]);
            *(__half2*)(ad + (g + 8) * AROW + c0)     = __floats2half2_rn(h[2], h[3]);
            *(__half2*)(ad + (g + 8) * AROW + c0 + 8) = __floats2half2_rn(h[6], h[7]);
        }

        cx00 = nx00; cx01 = nx01; cx10 = nx10; cx11 = nx11;

        // slab-local barrier: A publishes visible; all slab B reads complete
        asm volatile("bar.sync %0, 256;" :: "r"(barid) : "memory");

        // elected per slab: release W buffer p to the producer
        if (wt == 0 && n + 1 < LSITES) {
            asm volatile("mbarrier.arrive.shared.b64 _, [%0];"
                         :: "r"(mb + 16 + (uint32_t)(p * 8)) : "memory");
        }
    }

    __syncthreads();   // re-join slabs before reusing Wbuf region

    // dump h to smem (reuse Wbuf region) for the classifier
    float* Fh = (float*)smem;   // [32][HROW]
    {
        float* fr = Fh + kg * SLAB * HROW;
        fr[g * HROW + c0]           = h[0];
        fr[g * HROW + c0 + 1]       = h[1];
        fr[g * HROW + c0 + 8]       = h[4];
        fr[g * HROW + c0 + 9]       = h[5];
        fr[(g + 8) * HROW + c0]     = h[2];
        fr[(g + 8) * HROW + c0 + 1] = h[3];
        fr[(g + 8) * HROW + c0 + 8] = h[6];
        fr[(g + 8) * HROW + c0 + 9] = h[7];
    }
    __syncthreads();

    // classifier: logits = h @ V  (32 samples x 10 classes per CTA)
    if (tid < BC * NCLS) {
        int r = tid / NCLS, c = tid % NCLS;
        const float* hr = Fh + r * HROW;
        float s = 0.f;
#pragma unroll 8
        for (int a = 0; a < CHI; ++a) s += hr[a] * __ldg(V + a * NCLS + c);
        out[(size_t)(cta * BC + r) * NCLS + c] = s;
    }
}

// ---------------------------------------------------------------------------
extern "C" void kernel_launch(void* const* d_in, const int* in_sizes, int n_in,
                              void* d_out, int out_size) {
    const float* x = nullptr;  // 1024*2*784    = 1605632
    const float* W = nullptr;  // 784*2*128*128 = 25690112
    const float* V = nullptr;  // 128*10        = 1280
    for (int i = 0; i < n_in; ++i) {
        if (in_sizes[i] == BATCH * 2 * LSITES)            x = (const float*)d_in[i];
        else if (in_sizes[i] == LSITES * 2 * CHI * CHI)   W = (const float*)d_in[i];
        else if (in_sizes[i] == CHI * NCLS)               V = (const float*)d_in[i];
    }
    float* out = (float*)d_out;

    static_assert(SMEM_TOTAL == 152608, "smem layout");

    cudaFuncSetAttribute(prep_kernel, cudaFuncAttributeMaxDynamicSharedMemorySize, SITE_BYTES);
    cudaFuncSetAttribute(mps_kernel,  cudaFuncAttributeMaxDynamicSharedMemorySize, SMEM_TOTAL);

    prep_kernel<<<LSITES, 256, SITE_BYTES>>>(W);
    mps_kernel<<<NCTA, THREADS, SMEM_TOTAL>>>(x, V, out);
    (void)out_size;
}

// round 16
// speedup vs baseline: 1.5256x; 1.5256x over previous
#include <cuda_runtime.h>
#include <cuda_fp16.h>
#include <cstdint>
#include <cstddef>

// ----- problem constants -----
#define LSITES  784
#define CHI     128
#define BATCH   1024
#define NCLS    10
#define BC      16                 // samples per CTA
#define NCTA    (BATCH / BC)       // 64
#define THREADS 256
#define HROW    132                // classifier h row stride (floats)
#define AROW    136                // padded A row stride (halves), K=128
#define ABUF_HALVES (BC * AROW)    // 2176
#define ABUF_BYTES  (ABUF_HALVES * 2)   // 4352
// feature-0 half of W, smem-staged:  g_W0[site][b][k], k in [0,128)
#define W0ROW   136                // padded row stride (halves): 272B = 4-bank rotation
#define W0_SITE_HALVES (CHI * W0ROW)    // 17408
#define W0_SITE_BYTES  (W0_SITE_HALVES * 2)  // 34816
// feature-1 half of W, fragment-packed for direct LDG:
#define WF_SITE_U4 2048            // 8 warps * 8 chunks * 32 lanes = 32 KB/site
// smem layout
#define SMEM_A_OFF  (2 * W0_SITE_BYTES)             // 69632
#define SMEM_MB_OFF (SMEM_A_OFF + 2 * ABUF_BYTES)   // 78336
#define SMEM_TOTAL  (SMEM_MB_OFF + 16)              // 78352

__device__ __half g_W0[(size_t)LSITES * W0_SITE_HALVES];   // 27.3 MB
__device__ uint4  g_WF[(size_t)LSITES * WF_SITE_U4];       // 25.7 MB

// ---------------------------------------------------------------------------
// Prepass: W fp32 [n][k=s*128+a][b] -> (a) g_W0 half-K smem-layout,
//                                     (b) g_WF fragment-packed LDG-layout
// ---------------------------------------------------------------------------
__global__ void __launch_bounds__(256) prep_kernel(const float* __restrict__ W) {
    extern __shared__ __half sw[];   // [256][132] halves: sw[k*132 + b]
    const int n   = blockIdx.x;
    const int tid = threadIdx.x;
    const float* Wg = W + (size_t)n * (2 * CHI * CHI);

    for (int i = 0; i < 128; ++i) {
        int e = i * 256 + tid;            // e = k*128 + b
        int k = e >> 7;
        int b = e & 127;
        sw[k * 132 + b] = __float2half_rn(Wg[e]);
    }
    __syncthreads();

    // (a) g_W0: rows b, k-contiguous (k < 128), row stride W0ROW
    {
        const int w    = tid >> 5;
        const int lane = tid & 31;
        for (int r = 0; r < 16; ++r) {
            int b  = w * 16 + r;
            int k0 = lane * 4;            // 4 halves per lane -> 128 k total
            __align__(8) __half tmp[4];
#pragma unroll
            for (int j = 0; j < 4; ++j) tmp[j] = sw[(k0 + j) * 132 + b];
            *(uint2*)(&g_W0[(size_t)n * W0_SITE_HALVES + b * W0ROW + k0]) = *(uint2*)tmp;
        }
    }

    // (b) g_WF: fragment-packed, chunks cc=0..7 are k in [128,256)
    for (int i = 0; i < 8; ++i) {
        int idx  = i * 256 + tid;         // (w*8 + cc)*32 + lane
        int lane = idx & 31;
        int cc   = (idx >> 5) & 7;
        int w    = idx >> 8;
        int tg   = lane & 3;
        int g    = lane >> 2;
        int k0   = 128 + cc * 16;
        int b0   = w * 16 + g;
        int b1   = b0 + 8;

        uint4 v;
        {
            __half2 t;
            t = __halves2half2(sw[(k0 + 2*tg) * 132 + b0],     sw[(k0 + 2*tg + 1) * 132 + b0]);
            v.x = *reinterpret_cast<uint32_t*>(&t);
            t = __halves2half2(sw[(k0 + 8 + 2*tg) * 132 + b0], sw[(k0 + 9 + 2*tg) * 132 + b0]);
            v.y = *reinterpret_cast<uint32_t*>(&t);
            t = __halves2half2(sw[(k0 + 2*tg) * 132 + b1],     sw[(k0 + 2*tg + 1) * 132 + b1]);
            v.z = *reinterpret_cast<uint32_t*>(&t);
            t = __halves2half2(sw[(k0 + 8 + 2*tg) * 132 + b1], sw[(k0 + 9 + 2*tg) * 132 + b1]);
            v.w = *reinterpret_cast<uint32_t*>(&t);
        }
        g_WF[(size_t)n * WF_SITE_U4 + idx] = v;
    }
}

// ---------------------------------------------------------------------------
__device__ __forceinline__ void mbar_wait(uint32_t mbar, uint32_t parity) {
    asm volatile(
        "{\n\t.reg .pred P;\n"
        "W%=:\n\t"
        "mbarrier.try_wait.parity.acquire.cta.shared::cta.b64 P, [%0], %1, 0x989680;\n\t"
        "@!P bra W%=;\n\t}"
        :: "r"(mbar), "r"(parity) : "memory");
}

#define MMA16816(AC, A, B0, B1)                                               \
    asm volatile(                                                             \
        "mma.sync.aligned.m16n8k16.row.col.f32.f16.f16.f32 "                  \
        "{%0,%1,%2,%3}, {%4,%5,%6,%7}, {%8,%9}, {%0,%1,%2,%3};\n"             \
        : "+f"((AC)[0]), "+f"((AC)[1]), "+f"((AC)[2]), "+f"((AC)[3])          \
        : "r"((A)[0]), "r"((A)[1]), "r"((A)[2]), "r"((A)[3]), "r"(B0), "r"(B1))

// One site. P = buffer parity; PHF = full-barrier parity var (by name);
// BCUR/BNXT = feature-1 B fragment register ping-pong.
#define SITE_BODY(NN, P, PHF, BCUR, BNXT)                                     \
{                                                                             \
    const int n_ = (NN);                                                      \
    /* stage feature-0 W for site n+1 (TMA -> other smem buffer) */           \
    if (tid == 0 && n_ + 1 < LSITES) {                                        \
        const uint32_t mnext = mb + (uint32_t)((1 - (P)) * 8);                \
        asm volatile("mbarrier.arrive.expect_tx.shared.b64 _, [%0], %1;"      \
                     :: "r"(mnext), "r"((uint32_t)W0_SITE_BYTES) : "memory"); \
        asm volatile(                                                         \
            "cp.async.bulk.shared::cluster.global.mbarrier::complete_tx::bytes [%0], [%1], %2, [%3];" \
            :: "r"(wbuf_s + (uint32_t)((1 - (P)) * W0_SITE_BYTES)),           \
               "l"((const void*)(g_W0 + (size_t)(n_ + 1) * W0_SITE_HALVES)),  \
               "r"((uint32_t)W0_SITE_BYTES), "r"(mnext)                       \
            : "memory");                                                      \
    }                                                                         \
    /* stream feature-1 W fragments for site n+1 (LDG -> registers) */        \
    float nx00 = 0.f, nx01 = 0.f, nx10 = 0.f, nx11 = 0.f;                     \
    if (n_ + 1 < LSITES) {                                                    \
        const uint4* wp_ = wfptr + (size_t)(n_ + 1) * WF_SITE_U4;             \
        _Pragma("unroll")                                                     \
        for (int cc = 0; cc < 8; ++cc) {                                      \
            uint4 t_ = __ldg(wp_ + cc * 32);                                  \
            BNXT[cc][0] = t_.x; BNXT[cc][1] = t_.y;                           \
            BNXT[cc][2] = t_.z; BNXT[cc][3] = t_.w;                           \
        }                                                                     \
        nx00 = __ldg(px00 + n_ + 1); nx01 = __ldg(px01 + n_ + 1);             \
        nx10 = __ldg(px10 + n_ + 1); nx11 = __ldg(px11 + n_ + 1);             \
    }                                                                         \
    /* A fragments: 8 k-chunks of fp16(h), shared by both features */         \
    uint32_t a[8][4];                                                         \
    {                                                                         \
        const uint32_t ab_ = a_base + (uint32_t)((P) * ABUF_BYTES);           \
        _Pragma("unroll")                                                     \
        for (int ca = 0; ca < 8; ++ca) {                                      \
            asm volatile(                                                     \
                "ldmatrix.sync.aligned.m8n8.x4.shared.b16 {%0,%1,%2,%3}, [%4];\n" \
                : "=r"(a[ca][0]), "=r"(a[ca][1]), "=r"(a[ca][2]), "=r"(a[ca][3]) \
                : "r"(ab_ + (uint32_t)(ca * 32)));                            \
        }                                                                     \
    }                                                                         \
    /* wait for this site's feature-0 W buffer */                             \
    mbar_wait(mb + (uint32_t)((P) * 8), PHF); PHF ^= 1;                       \
    float acc0[8], acc1[8];                                                   \
    _Pragma("unroll")                                                         \
    for (int i = 0; i < 8; ++i) { acc0[i] = 0.f; acc1[i] = 0.f; }             \
    /* feature 0: B via ldmatrix from smem */                                 \
    {                                                                         \
        const uint32_t bl = b_base + (uint32_t)((P) * W0_SITE_BYTES);         \
        _Pragma("unroll")                                                     \
        for (int c = 0; c < 8; ++c) {                                         \
            uint32_t b0, b1, b2, b3;                                          \
            asm volatile(                                                     \
                "ldmatrix.sync.aligned.m8n8.x4.shared.b16 {%0,%1,%2,%3}, [%4];\n" \
                : "=r"(b0), "=r"(b1), "=r"(b2), "=r"(b3)                      \
                : "r"(bl + (uint32_t)(c * 32)));                              \
            MMA16816(acc0 + 0, a[c], b0, b1);                                 \
            MMA16816(acc0 + 4, a[c], b2, b3);                                 \
        }                                                                     \
    }                                                                         \
    /* feature 1: B from prefetched registers */                              \
    _Pragma("unroll")                                                         \
    for (int cc = 0; cc < 8; ++cc) {                                          \
        MMA16816(acc1 + 0, a[cc], BCUR[cc][0], BCUR[cc][1]);                  \
        MMA16816(acc1 + 4, a[cc], BCUR[cc][2], BCUR[cc][3]);                  \
    }                                                                         \
    /* fold: h += x0[row]*delta0 + x1[row]*delta1  (f32, registers) */        \
    h[0] += cx00 * acc0[0] + cx01 * acc1[0];                                  \
    h[1] += cx00 * acc0[1] + cx01 * acc1[1];                                  \
    h[2] += cx10 * acc0[2] + cx11 * acc1[2];                                  \
    h[3] += cx10 * acc0[3] + cx11 * acc1[3];                                  \
    h[4] += cx00 * acc0[4] + cx01 * acc1[4];                                  \
    h[5] += cx00 * acc0[5] + cx01 * acc1[5];                                  \
    h[6] += cx10 * acc0[6] + cx11 * acc1[6];                                  \
    h[7] += cx10 * acc0[7] + cx11 * acc1[7];                                  \
    cx00 = nx00; cx01 = nx01; cx10 = nx10; cx11 = nx11;                       \
    /* publish fp16(h) into next site's A buffer */                           \
    {                                                                         \
        __half* ad_ = Abuf + (1 - (P)) * ABUF_HALVES;                         \
        *(__half2*)(ad_ + g * AROW + c0)           = __floats2half2_rn(h[0], h[1]); \
        *(__half2*)(ad_ + g * AROW + c0 + 8)       = __floats2half2_rn(h[4], h[5]); \
        *(__half2*)(ad_ + (g + 8) * AROW + c0)     = __floats2half2_rn(h[2], h[3]); \
        *(__half2*)(ad_ + (g + 8) * AROW + c0 + 8) = __floats2half2_rn(h[6], h[7]); \
    }                                                                         \
    __syncthreads();                                                          \
}

// ---------------------------------------------------------------------------
// Main kernel: R4 structure; B split across two data paths
// (feature 0: TMA+ldmatrix through smem, feature 1: LDG straight to regs).
// ---------------------------------------------------------------------------
__global__ void __launch_bounds__(THREADS, 1) mps_kernel(const float* __restrict__ x,
                                                         const float* __restrict__ V,
                                                         float* __restrict__ out) {
    extern __shared__ char smem[];
    __half* Wbuf = (__half*)smem;                     // [2][W0_SITE_HALVES]
    __half* Abuf = (__half*)(smem + SMEM_A_OFF);      // [2][BC][AROW] fp16(h)
    const uint32_t mb = (uint32_t)__cvta_generic_to_shared(smem + SMEM_MB_OFF);

    const int tid  = threadIdx.x;
    const int cta  = blockIdx.x;
    const int w    = tid >> 5;               // warp 0..7 -> cols [w*16, w*16+16)
    const int lane = tid & 31;
    const int g    = lane >> 2;              // 0..7
    const int tg   = lane & 3;               // 0..3
    const int c0   = w * 16 + 2 * tg;        // owned h/delta column base

    // h register layout (matches acc fragments):
    //  h[0]=H[g][c0]   h[1]=H[g][c0+1]   h[2]=H[g+8][c0]   h[3]=H[g+8][c0+1]
    //  h[4]=H[g][c0+8] h[5]=H[g][c0+9]   h[6]=H[g+8][c0+8] h[7]=H[g+8][c0+9]
    float h[8];
#pragma unroll
    for (int i = 0; i < 8; ++i) h[i] = 1.0f;

    if (tid == 0) {
        asm volatile("mbarrier.init.shared.b64 [%0], 1;" :: "r"(mb)     : "memory");
        asm volatile("mbarrier.init.shared.b64 [%0], 1;" :: "r"(mb + 8) : "memory");
    }
    // init Abuf[0] = fp16(1)
    {
        const __half2 one2 = __floats2half2_rn(1.f, 1.f);
        *(__half2*)(Abuf + g * AROW + c0)           = one2;
        *(__half2*)(Abuf + g * AROW + c0 + 8)       = one2;
        *(__half2*)(Abuf + (g + 8) * AROW + c0)     = one2;
        *(__half2*)(Abuf + (g + 8) * AROW + c0 + 8) = one2;
    }
    __syncthreads();

    const uint32_t wbuf_s = (uint32_t)__cvta_generic_to_shared(Wbuf);
    const uint32_t abuf_s = (uint32_t)__cvta_generic_to_shared(Abuf);

    // prologue: stage feature-0 of site 0 into buffer 0
    if (tid == 0) {
        asm volatile("mbarrier.arrive.expect_tx.shared.b64 _, [%0], %1;"
                     :: "r"(mb), "r"((uint32_t)W0_SITE_BYTES) : "memory");
        asm volatile(
            "cp.async.bulk.shared::cluster.global.mbarrier::complete_tx::bytes [%0], [%1], %2, [%3];"
            :: "r"(wbuf_s), "l"((const void*)g_W0), "r"((uint32_t)W0_SITE_BYTES), "r"(mb)
            : "memory");
    }

    // per-thread x streams: samples cta*16+g and cta*16+g+8, features 0/1
    const int sg0 = cta * BC + g;
    const int sg1 = sg0 + 8;
    const float* px00 = x + ((size_t)sg0 * 2 + 0) * LSITES;
    const float* px01 = x + ((size_t)sg0 * 2 + 1) * LSITES;
    const float* px10 = x + ((size_t)sg1 * 2 + 0) * LSITES;
    const float* px11 = x + ((size_t)sg1 * 2 + 1) * LSITES;
    float cx00 = __ldg(px00), cx01 = __ldg(px01);
    float cx10 = __ldg(px10), cx11 = __ldg(px11);

    // A-ldmatrix lane address
    const uint32_t a_base = abuf_s + (uint32_t)((((lane & 15) * AROW) + ((lane >> 4) * 8)) * 2);
    // feature-0 B-ldmatrix lane address (row stride W0ROW, conflict-free)
    const int grp = lane >> 3;
    const int r8  = lane & 7;
    const int bn  = w * 16 + ((grp & 2) ? 8 : 0) + r8;
    const int bk  = (grp & 1) ? 8 : 0;
    const uint32_t b_base = wbuf_s + (uint32_t)((bn * W0ROW + bk) * 2);

    // feature-1 fragment stream base + ping-pong registers
    const uint4* wfptr = g_WF + (size_t)w * 256 + lane;
    uint32_t bP[8][4], bQ[8][4];
#pragma unroll
    for (int cc = 0; cc < 8; ++cc) {   // prologue: site 0 fragments
        uint4 t = __ldg(wfptr + cc * 32);
        bP[cc][0] = t.x; bP[cc][1] = t.y; bP[cc][2] = t.z; bP[cc][3] = t.w;
    }

    uint32_t phF0 = 0, phF1 = 0;

    for (int n = 0; n < LSITES; n += 2) {
        SITE_BODY(n,     0, phF0, bP, bQ);
        SITE_BODY(n + 1, 1, phF1, bQ, bP);
    }

    // dump h to smem (reuse Wbuf region) for the classifier
    float* Fh = (float*)smem;   // [16][HROW]
    Fh[g * HROW + c0]           = h[0];
    Fh[g * HROW + c0 + 1]       = h[1];
    Fh[g * HROW + c0 + 8]       = h[4];
    Fh[g * HROW + c0 + 9]       = h[5];
    Fh[(g + 8) * HROW + c0]     = h[2];
    Fh[(g + 8) * HROW + c0 + 1] = h[3];
    Fh[(g + 8) * HROW + c0 + 8] = h[6];
    Fh[(g + 8) * HROW + c0 + 9] = h[7];
    __syncthreads();

    // classifier: logits = h @ V  (16 samples x 10 classes per CTA)
    if (tid < BC * NCLS) {
        int r = tid / NCLS, c = tid % NCLS;
        const float* hr = Fh + r * HROW;
        float s = 0.f;
#pragma unroll 8
        for (int a = 0; a < CHI; ++a) s += hr[a] * __ldg(V + a * NCLS + c);
        out[(size_t)(cta * BC + r) * NCLS + c] = s;
    }
}

// ---------------------------------------------------------------------------
extern "C" void kernel_launch(void* const* d_in, const int* in_sizes, int n_in,
                              void* d_out, int out_size) {
    const float* x = nullptr;  // 1024*2*784    = 1605632
    const float* W = nullptr;  // 784*2*128*128 = 25690112
    const float* V = nullptr;  // 128*10        = 1280
    for (int i = 0; i < n_in; ++i) {
        if (in_sizes[i] == BATCH * 2 * LSITES)            x = (const float*)d_in[i];
        else if (in_sizes[i] == LSITES * 2 * CHI * CHI)   W = (const float*)d_in[i];
        else if (in_sizes[i] == CHI * NCLS)               V = (const float*)d_in[i];
    }
    float* out = (float*)d_out;

    static_assert(SMEM_TOTAL == 78352, "smem layout");

    cudaFuncSetAttribute(prep_kernel, cudaFuncAttributeMaxDynamicSharedMemorySize, 256 * 132 * 2);
    cudaFuncSetAttribute(mps_kernel,  cudaFuncAttributeMaxDynamicSharedMemorySize, SMEM_TOTAL);

    prep_kernel<<<LSITES, 256, 256 * 132 * 2>>>(W);
    mps_kernel<<<NCTA, THREADS, SMEM_TOTAL>>>(x, V, out);
    (void)out_size;
}

// round 17
// speedup vs baseline: 1.8086x; 1.1855x over previous
#include <cuda_runtime.h>
#include <cuda_fp16.h>
#include <cstdint>
#include <cstddef>

// ----- problem constants -----
#define LSITES  784
#define CHI     128
#define BATCH   1024
#define NCLS    10
#define WROW    264               // padded k-stride of transposed W (halves)
#define SITE_HALVES (CHI * WROW)  // 33792 halves per site
#define SITE_BYTES  (SITE_HALVES * 2)  // 67584 B per site
#define SLICE_BYTES  (16 * WROW * 2)   // 8448 B: one warp's 16 B-rows
#define SLICE_HALVES (16 * WROW)       // 4224
#define BC      16                // samples per CTA
#define NCTA    (BATCH / BC)      // 64
#define HROW    132               // classifier h row stride (floats)
#define AROW    136               // padded A row stride (halves), K=128
#define ABUF_HALVES (BC * AROW)   // 2176 halves
#define ABUF_BYTES  (ABUF_HALVES * 2)   // 4352
#define SMEM_A_OFF   (2 * SITE_BYTES)               // 135168
#define SMEM_MB_OFF  (SMEM_A_OFF + 2 * ABUF_BYTES)  // 143872: [warp][buf] 16 mbarriers
#define SMEM_TOTAL   (SMEM_MB_OFF + 128)            // 144000

// fp16 transposed weights: Wt[site][b][k], k = s*128 + a, row stride WROW
__device__ __half g_Wt[(size_t)LSITES * SITE_HALVES];   // ~50.5 MB static scratch

// ---------------------------------------------------------------------------
// Prepass: W fp32 [n][s][a][b]  ->  fp16 Wt [n][b][k=s*128+a], padded rows
// ---------------------------------------------------------------------------
__global__ void __launch_bounds__(256) prep_kernel(const float* __restrict__ W) {
    extern __shared__ __half sw[];   // [256][132] halves
    const int n   = blockIdx.x;
    const int tid = threadIdx.x;
    const float* Wg = W + (size_t)n * (2 * CHI * CHI);

    for (int i = 0; i < 128; ++i) {
        int e = i * 256 + tid;
        int k = e >> 7;
        int b = e & 127;
        sw[k * 132 + b] = __float2half_rn(Wg[e]);
    }
    __syncthreads();

    const int w    = tid >> 5;
    const int lane = tid & 31;
    for (int r = 0; r < 16; ++r) {
        int b  = w * 16 + r;
        int k0 = lane * 8;
        __align__(16) __half tmp[8];
#pragma unroll
        for (int j = 0; j < 8; ++j) tmp[j] = sw[(k0 + j) * 132 + b];
        *(uint4*)(&g_Wt[((size_t)n * CHI + b) * WROW + k0]) = *(uint4*)tmp;
    }
}

// ---------------------------------------------------------------------------
__device__ __forceinline__ void mbar_wait(uint32_t mbar, uint32_t parity) {
    asm volatile(
        "{\n\t.reg .pred P;\n"
        "W%=:\n\t"
        "mbarrier.try_wait.parity.acquire.cta.shared::cta.b64 P, [%0], %1, 0x989680;\n\t"
        "@!P bra W%=;\n\t}"
        :: "r"(mbar), "r"(parity) : "memory");
}

// lane-0 slice stage: expect_tx + bulk copy of one warp's 16 B-rows
__device__ __forceinline__ void stage_slice(uint32_t mbar, uint32_t dst,
                                            const void* src) {
    asm volatile("mbarrier.arrive.expect_tx.shared.b64 _, [%0], %1;"
                 :: "r"(mbar), "r"((uint32_t)SLICE_BYTES) : "memory");
    asm volatile(
        "cp.async.bulk.shared::cluster.global.mbarrier::complete_tx::bytes [%0], [%1], %2, [%3];"
        :: "r"(dst), "l"(src), "r"((uint32_t)SLICE_BYTES), "r"(mbar)
        : "memory");
}

// ---------------------------------------------------------------------------
// Main kernel: R4 structure with per-warp W slice staging.
// Warp w stages + waits ONLY its own 8.4 KB slice (own mbarrier, own lane-0
// producer, 2-site-deep pipeline). No cross-warp W coupling; one
// __syncthreads per site for the A exchange, as in R4.
// ---------------------------------------------------------------------------
__global__ void __launch_bounds__(256, 1) mps_kernel(const float* __restrict__ x,
                                                     const float* __restrict__ V,
                                                     float* __restrict__ out) {
    extern __shared__ char smem[];
    __half* Wbuf = (__half*)smem;                       // [2][SITE_HALVES]
    __half* Abuf = (__half*)(smem + SMEM_A_OFF);        // [2][BC][AROW] fp16(h)
    const uint32_t mb = (uint32_t)__cvta_generic_to_shared(smem + SMEM_MB_OFF);

    const int tid  = threadIdx.x;
    const int cta  = blockIdx.x;
    const int w    = tid >> 5;               // warp 0..7 -> N range [w*16, w*16+16)
    const int lane = tid & 31;
    const int g    = lane >> 2;              // 0..7
    const int tg   = lane & 3;               // 0..3
    const int c0   = w * 16 + 2 * tg;        // owned h/delta column base

    // h register layout (matches acc fragments):
    //  h[0]=H[g][c0]   h[1]=H[g][c0+1]   h[2]=H[g+8][c0]   h[3]=H[g+8][c0+1]
    //  h[4]=H[g][c0+8] h[5]=H[g][c0+9]   h[6]=H[g+8][c0+8] h[7]=H[g+8][c0+9]
    float h[8];
#pragma unroll
    for (int i = 0; i < 8; ++i) h[i] = 1.0f;

    // 16 mbarriers: [warp][buf], count 1, tx-based
    if (tid < 16) {
        asm volatile("mbarrier.init.shared.b64 [%0], 1;"
                     :: "r"(mb + (uint32_t)(tid * 8)) : "memory");
    }

    // init Abuf[0] = fp16(1)
    {
        const __half2 one2 = __floats2half2_rn(1.f, 1.f);
        *(__half2*)(Abuf + g * AROW + c0)           = one2;
        *(__half2*)(Abuf + g * AROW + c0 + 8)       = one2;
        *(__half2*)(Abuf + (g + 8) * AROW + c0)     = one2;
        *(__half2*)(Abuf + (g + 8) * AROW + c0 + 8) = one2;
    }
    __syncthreads();

    const uint32_t wbuf_s = (uint32_t)__cvta_generic_to_shared(Wbuf);
    const uint32_t abuf_s = (uint32_t)__cvta_generic_to_shared(Abuf);

    // this warp's slice addresses
    const uint32_t mb_w     = mb + (uint32_t)(w * 16);           // +0 buf0, +8 buf1
    const uint32_t slice_d0 = wbuf_s + (uint32_t)(w * SLICE_BYTES);
    const char*    slice_s  = (const char*)(g_Wt + (size_t)w * SLICE_HALVES);

    // prologue: each warp stages its slice for sites 0 (buf0) and 1 (buf1)
    if (lane == 0) {
        stage_slice(mb_w,     slice_d0,              slice_s);
        stage_slice(mb_w + 8, slice_d0 + SITE_BYTES, slice_s + (size_t)SITE_BYTES * 1
                    /* site 1 src: */ + 0);
    }
    // NOTE: slice source for site n is slice_s + n*SITE_BYTES (g_Wt site stride)

    // per-thread x streams: samples cta*16+g and cta*16+g+8, features 0/1
    const int sg0 = cta * BC + g;
    const int sg1 = sg0 + 8;
    const float* px00 = x + ((size_t)sg0 * 2 + 0) * LSITES;
    const float* px01 = x + ((size_t)sg0 * 2 + 1) * LSITES;
    const float* px10 = x + ((size_t)sg1 * 2 + 0) * LSITES;
    const float* px11 = x + ((size_t)sg1 * 2 + 1) * LSITES;
    float cx00 = __ldg(px00), cx01 = __ldg(px01);
    float cx10 = __ldg(px10), cx11 = __ldg(px11);

    // ldmatrix lane addresses
    const uint32_t a_base = abuf_s + (uint32_t)((((lane & 15) * AROW) + ((lane >> 4) * 8)) * 2);
    const int grp = lane >> 3;
    const int r8  = lane & 7;
    const int bn  = w * 16 + ((grp & 2) ? 8 : 0) + r8;
    const int bk  = (grp & 1) ? 8 : 0;
    const uint32_t b_base = wbuf_s + (uint32_t)((bn * WROW + bk) * 2);

    uint32_t ph0 = 0, ph1 = 0;   // per-warp full parities for buf0/buf1

    for (int n = 0; n < LSITES; ++n) {
        const int p = n & 1;

        // prefetch x for next site
        float nx00 = 0.f, nx01 = 0.f, nx10 = 0.f, nx11 = 0.f;
        if (n + 1 < LSITES) {
            nx00 = __ldg(px00 + n + 1); nx01 = __ldg(px01 + n + 1);
            nx10 = __ldg(px10 + n + 1); nx11 = __ldg(px11 + n + 1);
        }

        // A fragments: 8 chunks of fp16(h), shared by both GEMMs
        uint32_t a[8][4];
        {
            const uint32_t ab = a_base + (uint32_t)(p * ABUF_BYTES);
#pragma unroll
            for (int ca = 0; ca < 8; ++ca) {
                asm volatile(
                    "ldmatrix.sync.aligned.m8n8.x4.shared.b16 {%0,%1,%2,%3}, [%4];\n"
                    : "=r"(a[ca][0]), "=r"(a[ca][1]), "=r"(a[ca][2]), "=r"(a[ca][3])
                    : "r"(ab + (uint32_t)(ca * 32)));
            }
        }

        // wait for THIS WARP's slice of this site's buffer
        if (p) { mbar_wait(mb_w + 8, ph1); ph1 ^= 1; }
        else   { mbar_wait(mb_w,     ph0); ph0 ^= 1; }

        // two GEMMs (s = k-half), 4 independent acc chains of depth 8
        float acc0[8], acc1[8];
#pragma unroll
        for (int i = 0; i < 8; ++i) { acc0[i] = 0.f; acc1[i] = 0.f; }
        {
            const uint32_t bl = b_base + (uint32_t)(p * SITE_BYTES);
#pragma unroll
            for (int c = 0; c < 16; ++c) {
                const int ca = c & 7;
                float* acc = (c & 8) ? acc1 : acc0;
                uint32_t b0, b1, b2, b3;
                asm volatile(
                    "ldmatrix.sync.aligned.m8n8.x4.shared.b16 {%0,%1,%2,%3}, [%4];\n"
                    : "=r"(b0), "=r"(b1), "=r"(b2), "=r"(b3)
                    : "r"(bl + (uint32_t)(c * 32)));
                asm volatile(
                    "mma.sync.aligned.m16n8k16.row.col.f32.f16.f16.f32 "
                    "{%0,%1,%2,%3}, {%4,%5,%6,%7}, {%8,%9}, {%0,%1,%2,%3};\n"
                    : "+f"(acc[0]), "+f"(acc[1]), "+f"(acc[2]), "+f"(acc[3])
                    : "r"(a[ca][0]), "r"(a[ca][1]), "r"(a[ca][2]), "r"(a[ca][3]),
                      "r"(b0), "r"(b1));
                asm volatile(
                    "mma.sync.aligned.m16n8k16.row.col.f32.f16.f16.f32 "
                    "{%0,%1,%2,%3}, {%4,%5,%6,%7}, {%8,%9}, {%0,%1,%2,%3};\n"
                    : "+f"(acc[4]), "+f"(acc[5]), "+f"(acc[6]), "+f"(acc[7])
                    : "r"(a[ca][0]), "r"(a[ca][1]), "r"(a[ca][2]), "r"(a[ca][3]),
                      "r"(b2), "r"(b3));
            }
        }

        // warp-local 2-deep pipeline: this warp's reads of buffer p are done
        // (register dependency via the MMAs above) -> stage site n+2 into p.
        if (lane == 0 && n + 2 < LSITES) {
            stage_slice(mb_w + (uint32_t)(p * 8),
                        slice_d0 + (uint32_t)(p * SITE_BYTES),
                        slice_s + (size_t)(n + 2) * SITE_BYTES);
        }

        // fold: h += x0[row]*delta0 + x1[row]*delta1   (f32, register-only)
        h[0] += cx00 * acc0[0] + cx01 * acc1[0];
        h[1] += cx00 * acc0[1] + cx01 * acc1[1];
        h[2] += cx10 * acc0[2] + cx11 * acc1[2];
        h[3] += cx10 * acc0[3] + cx11 * acc1[3];
        h[4] += cx00 * acc0[4] + cx01 * acc1[4];
        h[5] += cx00 * acc0[5] + cx01 * acc1[5];
        h[6] += cx10 * acc0[6] + cx11 * acc1[6];
        h[7] += cx10 * acc0[7] + cx11 * acc1[7];

        // publish fp16(h) into next site's A buffer
        {
            __half* ad = Abuf + (1 - p) * ABUF_HALVES;
            *(__half2*)(ad + g * AROW + c0)           = __floats2half2_rn(h[0], h[1]);
            *(__half2*)(ad + g * AROW + c0 + 8)       = __floats2half2_rn(h[4], h[5]);
            *(__half2*)(ad + (g + 8) * AROW + c0)     = __floats2half2_rn(h[2], h[3]);
            *(__half2*)(ad + (g + 8) * AROW + c0 + 8) = __floats2half2_rn(h[6], h[7]);
        }

        cx00 = nx00; cx01 = nx01; cx10 = nx10; cx11 = nx11;
        __syncthreads();
    }

    // dump h to smem (reuse Wbuf region) for the classifier
    float* Fh = (float*)smem;   // [16][HROW]
    Fh[g * HROW + c0]           = h[0];
    Fh[g * HROW + c0 + 1]       = h[1];
    Fh[g * HROW + c0 + 8]       = h[4];
    Fh[g * HROW + c0 + 9]       = h[5];
    Fh[(g + 8) * HROW + c0]     = h[2];
    Fh[(g + 8) * HROW + c0 + 1] = h[3];
    Fh[(g + 8) * HROW + c0 + 8] = h[6];
    Fh[(g + 8) * HROW + c0 + 9] = h[7];
    __syncthreads();

    // classifier: logits = h @ V  (16 samples x 10 classes per CTA)
    if (tid < BC * NCLS) {
        int r = tid / NCLS, c = tid % NCLS;
        const float* hr = Fh + r * HROW;
        float s = 0.f;
#pragma unroll 8
        for (int a = 0; a < CHI; ++a) s += hr[a] * __ldg(V + a * NCLS + c);
        out[(size_t)(cta * BC + r) * NCLS + c] = s;
    }
}

// ---------------------------------------------------------------------------
extern "C" void kernel_launch(void* const* d_in, const int* in_sizes, int n_in,
                              void* d_out, int out_size) {
    const float* x = nullptr;  // 1024*2*784    = 1605632
    const float* W = nullptr;  // 784*2*128*128 = 25690112
    const float* V = nullptr;  // 128*10        = 1280
    for (int i = 0; i < n_in; ++i) {
        if (in_sizes[i] == BATCH * 2 * LSITES)            x = (const float*)d_in[i];
        else if (in_sizes[i] == LSITES * 2 * CHI * CHI)   W = (const float*)d_in[i];
        else if (in_sizes[i] == CHI * NCLS)               V = (const float*)d_in[i];
    }
    float* out = (float*)d_out;

    static_assert(SMEM_TOTAL == 144000, "smem layout");

    cudaFuncSetAttribute(prep_kernel, cudaFuncAttributeMaxDynamicSharedMemorySize, SITE_BYTES);
    cudaFuncSetAttribute(mps_kernel,  cudaFuncAttributeMaxDynamicSharedMemorySize, SMEM_TOTAL);

    prep_kernel<<<LSITES, 256, SITE_BYTES>>>(W);
    mps_kernel<<<NCTA, 256, SMEM_TOTAL>>>(x, V, out);
    (void)out_size;
}